// round 13
// baseline (speedup 1.0000x reference)
#include <cuda_runtime.h>
#include <math.h>

// Problem constants
#define BSZ    8
#define SEQ    1024
#define HEADS  8
#define HDIM   64
#define CDIM   512          // HEADS*HDIM
#define PROJN  1024         // 2*CDIM
// HDIM^-0.5 * log2(e): scale folded together with the exp->exp2 conversion.
// softmax_h(exp2(y_h - my)) == softmax_h(exp(x_h - mx)) for y = x*log2(e).
#define ATT_SCALE_L2E (0.125f * 1.44269504088896340736f)

typedef unsigned long long u64t;

// ---------------------------------------------------------------------------
// Packed fp32x2 helpers (sm_100+). Lane-wise IEEE fp32: bit-identical to FFMA.
// ---------------------------------------------------------------------------
__device__ __forceinline__ u64t pack2(float lo, float hi) {
    u64t r;
    asm("mov.b64 %0, {%1, %2};" : "=l"(r) : "f"(lo), "f"(hi));
    return r;
}
__device__ __forceinline__ void fma2(u64t& acc, u64t a, u64t b) {
    asm("fma.rn.f32x2 %0, %1, %2, %0;" : "+l"(acc) : "l"(a), "l"(b));
}
__device__ __forceinline__ float2 unpack2(u64t v) {
    float2 f;
    asm("mov.b64 {%0, %1}, %2;" : "=f"(f.x), "=f"(f.y) : "l"(v));
    return f;
}

// Scratch for projection outputs: [b*n][1024], cols 0:512 = q, 512:1024 = k
__device__ float g_nqk[BSZ * SEQ * PROJN];
__device__ float g_rqk[BSZ * SEQ * PROJN];

// ---------------------------------------------------------------------------
// Projection GEMM (both modalities in one launch; z selects modality):
//   C[8192][1024] = A[8192][512] @ W[512][1024] + bias
// 128x128 block tile, 8x8 thread tile, BK=16, 256 threads.
// __launch_bounds__(256, 2): 2 CTAs/SM (smem 16.9KB, ~110 regs < 128 cap) so
// the co-resident CTA's FMA2 stream hides this CTA's barrier/LDG bubbles.
// ---------------------------------------------------------------------------
__global__ __launch_bounds__(256, 2)
void proj_kernel(const float* __restrict__ A0, const float* __restrict__ W0,
                 const float* __restrict__ bias0, float* __restrict__ C0,
                 const float* __restrict__ A1, const float* __restrict__ W1,
                 const float* __restrict__ bias1, float* __restrict__ C1)
{
    __shared__ float As[16][132];  // transposed A tile: As[k][m]
    __shared__ float Bs[16][132];  // Bs[k][n] (132 even -> 8B-aligned pairs)

    const int z = blockIdx.z;
    const float* A    = z ? A1 : A0;
    const float* W    = z ? W1 : W0;
    const float* bias = z ? bias1 : bias0;
    float*       Cout = z ? C1 : C0;

    const int tid = threadIdx.x;
    const int bn  = blockIdx.x * 128;
    const int bm  = blockIdx.y * 128;
    const int ty  = tid >> 4;      // 0..15
    const int tx  = tid & 15;      // 0..15

    const int arow = tid >> 1;           // 0..127
    const int acol = (tid & 1) * 8;      // 0 or 8
    const int brow = tid >> 4;           // 0..15
    const int bcol = (tid & 15) * 8;     // 0..120

    const float* Ap = A + (size_t)(bm + arow) * CDIM + acol;
    const float* Wp = W + (size_t)brow * PROJN + bn + bcol;

    // acc2[i][j2]: row i (0..7) x packed col-pair j2
    u64t acc2[8][4];
#pragma unroll
    for (int i = 0; i < 8; i++)
#pragma unroll
        for (int j = 0; j < 4; j++) acc2[i][j] = 0ull;

    for (int k0 = 0; k0 < CDIM; k0 += 16) {
        // LDGs issued before the barrier: latency overlaps barrier wait
        float4 av0 = *(const float4*)(Ap + k0);
        float4 av1 = *(const float4*)(Ap + k0 + 4);
        float4 bv0 = *(const float4*)(Wp + (size_t)k0 * PROJN);
        float4 bv1 = *(const float4*)(Wp + (size_t)k0 * PROJN + 4);
        __syncthreads();
        As[acol + 0][arow] = av0.x;
        As[acol + 1][arow] = av0.y;
        As[acol + 2][arow] = av0.z;
        As[acol + 3][arow] = av0.w;
        As[acol + 4][arow] = av1.x;
        As[acol + 5][arow] = av1.y;
        As[acol + 6][arow] = av1.z;
        As[acol + 7][arow] = av1.w;
        *(float4*)&Bs[brow][bcol]     = bv0;
        *(float4*)&Bs[brow][bcol + 4] = bv1;
        __syncthreads();
#pragma unroll
        for (int k = 0; k < 16; k++) {
            float af[8];
            *(float4*)&af[0] = *(const float4*)&As[k][ty * 4];
            *(float4*)&af[4] = *(const float4*)&As[k][64 + ty * 4];

            u64t bp[4];
            bp[0] = *(const u64t*)&Bs[k][tx * 4];
            bp[1] = *(const u64t*)&Bs[k][tx * 4 + 2];
            bp[2] = *(const u64t*)&Bs[k][64 + tx * 4];
            bp[3] = *(const u64t*)&Bs[k][64 + tx * 4 + 2];

#pragma unroll
            for (int i = 0; i < 8; i++) {
                const u64t aa = pack2(af[i], af[i]);
                fma2(acc2[i][0], aa, bp[0]);
                fma2(acc2[i][1], aa, bp[1]);
                fma2(acc2[i][2], aa, bp[2]);
                fma2(acc2[i][3], aa, bp[3]);
            }
        }
    }

    const int c0 = tx * 4;
    const int c1 = 64 + tx * 4;
    // Bias is i-invariant: load once, vectorized (2 LDG.128 instead of 16 LDG)
    const float4 bb0 = *(const float4*)(bias + bn + c0);
    const float4 bb1 = *(const float4*)(bias + bn + c1);
#pragma unroll
    for (int i = 0; i < 8; i++) {
        const int row = bm + ((i < 4) ? (ty * 4 + i) : (60 + ty * 4 + i));
        float* crow = Cout + (size_t)row * PROJN + bn;
        float2 p0 = unpack2(acc2[i][0]);
        float2 p1 = unpack2(acc2[i][1]);
        float2 p2 = unpack2(acc2[i][2]);
        float2 p3 = unpack2(acc2[i][3]);
        float4 v0, v1;
        v0.x = p0.x + bb0.x;
        v0.y = p0.y + bb0.y;
        v0.z = p1.x + bb0.z;
        v0.w = p1.y + bb0.w;
        v1.x = p2.x + bb1.x;
        v1.y = p2.y + bb1.y;
        v1.z = p3.x + bb1.z;
        v1.w = p3.y + bb1.w;
        *(float4*)(crow + c0) = v0;
        *(float4*)(crow + c1) = v1;
    }
}

// ---------------------------------------------------------------------------
// Fused attention with head-axis softmax (both modalities in one launch).
//   S[h][n][m] = SCALE * sum_d Q[n][h*64+d] * K[m][h*64+d]
//   P = softmax over h (8 values per (n,m))
//   O[n][h*64+d] += sum_m P[h][n][m] * V[m][h*64+d]
// Block = (b, 32 n-rows, modality z). 256 threads, 32-row m tiles.
// K loads hoisted above the barrier (transpose needs registers);
// V tile copied with cp.async (straight 16B copy), latency hidden by softmax.
// Softmax uses exp2 with log2(e) pre-folded into the S scale (see ATT_SCALE_L2E).
// ---------------------------------------------------------------------------
#define TN 32
#define TM 32
#define QKSTR 34
#define VSTR  520
#define SROW  33
#define SHSTR 1064                   // 32*33 + 8 (per-head stride, bank-skewed)
#define SM_KV (512 * QKSTR)          // 17408 floats
#define SM_S  (2 * 512 * QKSTR)     // 34816 floats
#define SMEM_FLOATS (SM_S + HEADS * SHSTR)   // 43328 floats = 173312 bytes
#define SMEM_BYTES (SMEM_FLOATS * 4)

__global__ __launch_bounds__(256)
void attn_kernel(const float* __restrict__ nqk, const float* __restrict__ rqk,
                 const float* __restrict__ nvg, const float* __restrict__ rvg,
                 float* __restrict__ outg)
{
    extern __shared__ float sm[];
    float* Qs  = sm;
    float* KVs = sm + SM_KV;
    float* Ss  = sm + SM_S;

    const int tid = threadIdx.x;
    const int b   = blockIdx.y;
    const int n0  = blockIdx.x * TN;
    const int z   = blockIdx.z;

    // z=0: Q=noise_q, K=rgb_k, V=rv, O=out(first half)
    // z=1: Q=rgb_q,   K=noise_k, V=nv, O=out(second half)
    const float* Qg = z ? rqk : nqk;
    const float* Kg = (z ? nqk : rqk) + CDIM;
    const float* Vg = z ? nvg : rvg;
    float*       Og = outg + (size_t)z * BSZ * SEQ * CDIM;

    const int lrow = tid >> 3;   // 0..31 (tile row for cooperative loads)
    const int lcv  = tid & 7;    // 0..7  (vec-col group)

    // --- load Q tile, transposed: Qs[c*QKSTR + n] ---
    {
        const float* qrow = Qg + (size_t)(b * SEQ + n0 + lrow) * PROJN;
#pragma unroll
        for (int j = 0; j < 16; j++) {
            const int c = (lcv + j * 8) * 4;
            float4 v = *(const float4*)(qrow + c);
            Qs[(c + 0) * QKSTR + lrow] = v.x;
            Qs[(c + 1) * QKSTR + lrow] = v.y;
            Qs[(c + 2) * QKSTR + lrow] = v.z;
            Qs[(c + 3) * QKSTR + lrow] = v.w;
        }
    }

    // phase-1 ids: warp = one head; 4n x 8m micro-tile per lane
    const int hg   = tid >> 5;
    const int lane = tid & 31;
    const int rg   = lane >> 2;  // rows rg*4..+3
    const int cg   = lane & 3;   // cols cg*8..+7

    // phase-3 ids: 8n x 8c micro-tile per thread
    const int rb = tid >> 6;     // rows rb*8..+7
    const int cb = tid & 63;     // cols cb*8..+7
    const int h3 = cb >> 3;      // head owning those 8 cols

    // V-tile cp.async destination (shared-space address) and source row
    const unsigned int vdst_base =
        (unsigned int)__cvta_generic_to_shared(&KVs[lrow * VSTR]);

    // o2[j][i2]: row (rb*8+j), packed col pair (2*i2, 2*i2+1)
    u64t o2[8][4];
#pragma unroll
    for (int j = 0; j < 8; j++)
#pragma unroll
        for (int i = 0; i < 4; i++) o2[j][i] = 0ull;

    for (int m0 = 0; m0 < SEQ; m0 += TM) {
        // --- K tile LDGs issued BEFORE the barrier (global-only: race-free).
        //     Latency overlaps barrier wait + prior iter's phase-3 tail. ---
        float4 kreg[16];
        {
            const float* krow = Kg + (size_t)(b * SEQ + m0 + lrow) * PROJN;
#pragma unroll
            for (int j = 0; j < 16; j++)
                kreg[j] = *(const float4*)(krow + (lcv + j * 8) * 4);
        }
        __syncthreads();   // prior iter's phase-3 done with KVs(V) & Ss

        // --- store K tile, transposed: KVs[c*QKSTR + m] ---
#pragma unroll
        for (int j = 0; j < 16; j++) {
            const int c = (lcv + j * 8) * 4;
            KVs[(c + 0) * QKSTR + lrow] = kreg[j].x;
            KVs[(c + 1) * QKSTR + lrow] = kreg[j].y;
            KVs[(c + 2) * QKSTR + lrow] = kreg[j].z;
            KVs[(c + 3) * QKSTR + lrow] = kreg[j].w;
        }
        __syncthreads();

        // --- phase 1: S[h] = Q_h @ K_h^T (scaled) ---
        // K pairs load directly as 64-bit (already packed along m).
        {
            u64t s2[4][4];   // [row i][col pair j2]
#pragma unroll
            for (int i = 0; i < 4; i++)
#pragma unroll
                for (int j = 0; j < 4; j++) s2[i][j] = 0ull;

            const float* qh = Qs + hg * 64 * QKSTR + rg * 4;
            const u64t* khp = (const u64t*)(KVs + hg * 64 * QKSTR + cg * 8);
#pragma unroll 8
            for (int k = 0; k < 64; k++) {
                const float a0 = qh[k * QKSTR + 0];
                const float a1 = qh[k * QKSTR + 1];
                const float a2v = qh[k * QKSTR + 2];
                const float a3 = qh[k * QKSTR + 3];
                const u64t aa0 = pack2(a0, a0);
                const u64t aa1 = pack2(a1, a1);
                const u64t aa2 = pack2(a2v, a2v);
                const u64t aa3 = pack2(a3, a3);
                const u64t* kr = khp + k * (QKSTR / 2);
#pragma unroll
                for (int j2 = 0; j2 < 4; j2++) {
                    const u64t bb = kr[j2];
                    fma2(s2[0][j2], aa0, bb);
                    fma2(s2[1][j2], aa1, bb);
                    fma2(s2[2][j2], aa2, bb);
                    fma2(s2[3][j2], aa3, bb);
                }
            }
            float* sdst = Ss + hg * SHSTR;
#pragma unroll
            for (int i = 0; i < 4; i++)
#pragma unroll
                for (int j2 = 0; j2 < 4; j2++) {
                    float2 t = unpack2(s2[i][j2]);
                    sdst[(rg * 4 + i) * SROW + cg * 8 + 2 * j2 + 0] = t.x * ATT_SCALE_L2E;
                    sdst[(rg * 4 + i) * SROW + cg * 8 + 2 * j2 + 1] = t.y * ATT_SCALE_L2E;
                }
        }
        __syncthreads();   // phase-1 done reading KVs(K); Ss fully written

        // --- V tile: async 16B copies global->shared (straight copy, no
        //     transpose). In flight during softmax; drained before sync. ---
        {
            const float* vrow = Vg + (size_t)(b * SEQ + m0 + lrow) * CDIM;
#pragma unroll
            for (int j = 0; j < 16; j++) {
                const int c4 = (lcv + j * 8) * 4;
                asm volatile(
                    "cp.async.cg.shared.global [%0], [%1], 16;"
                    :: "r"(vdst_base + (unsigned int)(c4 * 4)),
                       "l"(vrow + c4) : "memory");
            }
            asm volatile("cp.async.commit_group;" ::: "memory");
        }

        // --- softmax over heads (8 values per (n,m) pair), in place.
        //     Values are pre-scaled by log2(e): exp2 replaces exp. ---
#pragma unroll
        for (int i = 0; i < 4; i++) {
            const int p = i * 256 + tid;           // 0..1023
            float* base = Ss + (p >> 5) * SROW + (p & 31);
            float v[8];
            float mx = -1e30f;
#pragma unroll
            for (int h = 0; h < 8; h++) {
                v[h] = base[h * SHSTR];
                mx = fmaxf(mx, v[h]);
            }
            float sum = 0.f;
#pragma unroll
            for (int h = 0; h < 8; h++) {
                v[h] = exp2f(v[h] - mx);
                sum += v[h];
            }
            const float inv = __fdividef(1.f, sum);
#pragma unroll
            for (int h = 0; h < 8; h++)
                base[h * SHSTR] = v[h] * inv;
        }
        asm volatile("cp.async.wait_group 0;" ::: "memory");
        __syncthreads();

        // --- phase 3: O += P (head-broadcast) * V ---
        {
            const float* Ph = Ss + h3 * SHSTR + rb * 8 * SROW;
            const u64t* Vbp = (const u64t*)(KVs + cb * 8);
#pragma unroll 2
            for (int m = 0; m < TM; m++) {
                u64t pp[8];
#pragma unroll
                for (int j = 0; j < 8; j++) {
                    const float pj = Ph[j * SROW + m];
                    pp[j] = pack2(pj, pj);
                }
                const u64t* vr = Vbp + m * (VSTR / 2);
                u64t vv[4];
                vv[0] = vr[0];
                vv[1] = vr[1];
                vv[2] = vr[2];
                vv[3] = vr[3];
#pragma unroll
                for (int j = 0; j < 8; j++) {
                    fma2(o2[j][0], pp[j], vv[0]);
                    fma2(o2[j][1], pp[j], vv[1]);
                    fma2(o2[j][2], pp[j], vv[2]);
                    fma2(o2[j][3], pp[j], vv[3]);
                }
            }
        }
    }

    // --- write O ---
    float* ob = Og + (size_t)(b * SEQ + n0) * CDIM + cb * 8;
#pragma unroll
    for (int j = 0; j < 8; j++) {
        float o[8];
#pragma unroll
        for (int i2 = 0; i2 < 4; i2++) {
            float2 t = unpack2(o2[j][i2]);
            o[2 * i2 + 0] = t.x;
            o[2 * i2 + 1] = t.y;
        }
        const int row = rb * 8 + j;
        *(float4*)(ob + (size_t)row * CDIM) =
            make_float4(o[0], o[1], o[2], o[3]);
        *(float4*)(ob + (size_t)row * CDIM + 4) =
            make_float4(o[4], o[5], o[6], o[7]);
    }
}

// ---------------------------------------------------------------------------
extern "C" void kernel_launch(void* const* d_in, const int* in_sizes, int n_in,
                              void* d_out, int out_size)
{
    const float* nv = (const float*)d_in[0];
    const float* rv = (const float*)d_in[1];
    const float* Wn = (const float*)d_in[2];
    const float* bn = (const float*)d_in[3];
    const float* Wr = (const float*)d_in[4];
    const float* br = (const float*)d_in[5];
    float* out = (float*)d_out;

    float *nqk, *rqk;
    cudaGetSymbolAddress((void**)&nqk, g_nqk);
    cudaGetSymbolAddress((void**)&rqk, g_rqk);

    cudaFuncSetAttribute(attn_kernel,
                         cudaFuncAttributeMaxDynamicSharedMemorySize, SMEM_BYTES);

    // Both projections in one launch (z = modality)
    dim3 pgrid(PROJN / 128, (BSZ * SEQ) / 128, 2);   // (8, 64, 2)
    proj_kernel<<<pgrid, 256>>>(nv, Wn, bn, nqk,
                                rv, Wr, br, rqk);

    // Both attention passes in one launch (z = modality)
    dim3 agrid(SEQ / TN, BSZ, 2);                    // (32, 8, 2)
    attn_kernel<<<agrid, 256, SMEM_BYTES>>>(nqk, rqk, nv, rv, out);
}